// round 4
// baseline (speedup 1.0000x reference)
#include <cuda_runtime.h>
#include <cuda_bf16.h>
#include <cstdint>
#include <math.h>

#define BATCH 262144
#define GD 16
#define HID 256
#define RR 16
#define ZD 128
#define MTILE 64
#define NBLK (BATCH / MTILE)

// padded smem strides (floats) for conflict-free mma fragment LDS
#define XS_S 20
#define W1_S 264
#define H_S  260
#define BB_S 36      // W2 chunk row stride
#define W3_S 24

// scratch between kernels (device globals: allocation-free)
__device__ float g_lamg[BATCH];
__device__ float g_d[BATCH * RR];

// raw fp32 bits into mma.tf32 (HW truncates low mantissa bits; no cvt needed)
__device__ __forceinline__ uint32_t fbits(float x) { return __float_as_uint(x); }

__device__ __forceinline__ void mma8(float d[4], const uint32_t a[4],
                                     const uint32_t b[2], const float c[4]) {
    asm volatile(
        "mma.sync.aligned.m16n8k8.row.col.f32.tf32.tf32.f32 "
        "{%0,%1,%2,%3}, {%4,%5,%6,%7}, {%8,%9}, {%10,%11,%12,%13};\n"
        : "=f"(d[0]), "=f"(d[1]), "=f"(d[2]), "=f"(d[3])
        : "r"(a[0]), "r"(a[1]), "r"(a[2]), "r"(a[3]),
          "r"(b[0]), "r"(b[1]),
          "f"(c[0]), "f"(c[1]), "f"(c[2]), "f"(c[3]));
}

__device__ __forceinline__ void cpa16(float* s, const float* g) {
    uint32_t sa = (uint32_t)__cvta_generic_to_shared(s);
    asm volatile("cp.async.cg.shared.global [%0], [%1], 16;\n" ::"r"(sa), "l"(g));
}
__device__ __forceinline__ void cpcommit() { asm volatile("cp.async.commit_group;\n"); }
template <int N>
__device__ __forceinline__ void cpwait() { asm volatile("cp.async.wait_group %0;\n" ::"n"(N)); }

__device__ __forceinline__ float nan0(float v) { return isfinite(v) ? v : 0.f; }
__device__ __forceinline__ float silu_f(float x) { return x * (1.f / (1.f + __expf(-x))); }

// prefetch one K=16 x N=32 chunk of W2 for column group wn (lane-parallel)
__device__ __forceinline__ void prefetch_w2(float* dst, const float* __restrict__ W2,
                                            int chunk, int cbase, int lane) {
#pragma unroll
    for (int i = 0; i < 4; i++) {
        int idx = i * 32 + lane;          // 128 granules = 16 rows x 8 x 16B
        int kr = idx >> 3, gc = (idx & 7) << 2;
        cpa16(dst + kr * BB_S + gc, &W2[(size_t)(chunk * 16 + kr) * 256 + cbase + gc]);
    }
    cpcommit();
}

// ============================================================================
// Kernel 1: fused MLP  pt -> (lam_g, d[r] = lam_para[r] - lam_g)
// 512 threads (16 warps). GEMM2 mainloop has NO block barriers:
// each column pair streams its own W2 chunks through a private 4-deep ring,
// synced by a 64-thread named barrier.
// ============================================================================
__global__ void __launch_bounds__(512, 1) mlp_kernel(
    const float* __restrict__ pt, const float* __restrict__ dt_norm_g,
    const float* __restrict__ U,
    const float* __restrict__ W1, const float* __restrict__ b1,
    const float* __restrict__ W2, const float* __restrict__ b2,
    const float* __restrict__ W3, const float* __restrict__ b3) {
    extern __shared__ float sm[];
    float* xs  = sm;           // 64*20   = 1280
    float* w1s = sm + 1280;    // 16*264  = 4224
    float* h1s = sm + 5504;    // 64*260  = 16640 (reused as hpart in GEMM3)
    float* h2s = sm + 22144;   // 64*260  = 16640
    float* bb  = sm + 38784;   // 8 groups * 4 bufs * 16*36 = 18432 (reused as w3s)
    // total 57216 floats = 228864 B dynamic

    __shared__ float b1s[256], b2s[256], b3s[16], cn2s[16];

    const int tid = threadIdx.x;
    const int wid = tid >> 5, lane = tid & 31;
    const int g = lane >> 2, q = lane & 3;
    const int r0 = blockIdx.x * MTILE;

    // warp tiling for GEMM1/GEMM2: 2 x 8 warps, each 32 rows x 32 cols
    const int wm = wid >> 3, wn = wid & 7;
    const int rbase = wm * 32, cbase = wn * 32;
    float* bwn = bb + wn * (4 * 16 * BB_S);   // this column group's 4-buffer ring

    // --- kick off W2 chunks 0..2 (producer warp of each pair only) ---
    if (wm == 0) {
#pragma unroll
        for (int c = 0; c < 3; c++)
            prefetch_w2(bwn + c * (16 * BB_S), W2, c, cbase, lane);
    }

    // --- stage x tile (nan0) ---
#pragma unroll
    for (int i = 0; i < 2; i++) {
        int idx = tid + i * 512;                   // < 1024
        int rr = idx >> 4, cc = idx & 15;
        xs[rr * XS_S + cc] = nan0(pt[(size_t)(r0 + rr) * GD + cc]);
    }
    // --- stage W1 ---
#pragma unroll
    for (int i = 0; i < 8; i++) {
        int idx = tid + i * 512;                   // < 4096
        int kk = idx >> 8, cc = idx & 255;
        w1s[kk * W1_S + cc] = W1[kk * 256 + cc];
    }
    if (tid < 256) {
        b1s[tid] = b1[tid];
        b2s[tid] = b2[tid];
    }
    if (tid < 16) {
        b3s[tid] = b3[tid];
        float s = 0.f;
        for (int j = 0; j < ZD; j++) {
            float u = U[j * RR + tid];
            s += u * u;
        }
        cn2s[tid] = s;
    }
    // --- prefetch W3 into registers (staged to smem after GEMM2) ---
    float w3reg[8];
#pragma unroll
    for (int i = 0; i < 8; i++) w3reg[i] = W3[tid + i * 512];   // 4096 = 256*16
    __syncthreads();

    // ================= GEMM1: h1 = silu(x @ W1 + b1) =================
    {
#pragma unroll
        for (int mt = 0; mt < 2; mt++) {
#pragma unroll
            for (int nt = 0; nt < 4; nt++) {
                float acc[4] = {0.f, 0.f, 0.f, 0.f};
#pragma unroll
                for (int ks = 0; ks < 2; ks++) {
                    int k0 = ks * 8;
                    int ra = rbase + mt * 16;
                    uint32_t a[4] = {
                        fbits(xs[(ra + g) * XS_S + k0 + q]),
                        fbits(xs[(ra + g + 8) * XS_S + k0 + q]),
                        fbits(xs[(ra + g) * XS_S + k0 + q + 4]),
                        fbits(xs[(ra + g + 8) * XS_S + k0 + q + 4])};
                    int cb = cbase + nt * 8;
                    uint32_t b[2] = {fbits(w1s[(k0 + q) * W1_S + cb + g]),
                                     fbits(w1s[(k0 + q + 4) * W1_S + cb + g])};
                    mma8(acc, a, b, acc);
                }
                int rr = rbase + mt * 16, cc = cbase + nt * 8;
                h1s[(rr + g) * H_S + cc + 2 * q]     = silu_f(acc[0] + b1s[cc + 2 * q]);
                h1s[(rr + g) * H_S + cc + 2 * q + 1] = silu_f(acc[1] + b1s[cc + 2 * q + 1]);
                h1s[(rr + g + 8) * H_S + cc + 2 * q]     = silu_f(acc[2] + b1s[cc + 2 * q]);
                h1s[(rr + g + 8) * H_S + cc + 2 * q + 1] = silu_f(acc[3] + b1s[cc + 2 * q + 1]);
            }
        }
    }
    __syncthreads();

    // ================= GEMM2: h2 = silu(h1 @ W2 + b2) =================
    // 16 chunks of K=16. Pair-private ring, named-barrier sync, no block sync.
    {
        float acc[2][4][4];
#pragma unroll
        for (int mt = 0; mt < 2; mt++)
#pragma unroll
            for (int nt = 0; nt < 4; nt++)
#pragma unroll
                for (int i = 0; i < 4; i++) acc[mt][nt][i] = 0.f;

#pragma unroll 4
        for (int c = 0; c < 16; c++) {
            if (wm == 0) {
                if (c <= 13) cpwait<2>();
                else if (c == 14) cpwait<1>();
                else cpwait<0>();
            }
            asm volatile("bar.sync %0, 64;" ::"r"(1 + wn) : "memory");
            const float* wb = bwn + (c & 3) * (16 * BB_S);
#pragma unroll
            for (int ks = 0; ks < 2; ks++) {
                int kg = c * 16 + ks * 8;   // global K for A (h1)
                int kl = ks * 8;            // local K within chunk
                uint32_t a[2][4];
#pragma unroll
                for (int mt = 0; mt < 2; mt++) {
                    int ra = rbase + mt * 16;
                    a[mt][0] = fbits(h1s[(ra + g) * H_S + kg + q]);
                    a[mt][1] = fbits(h1s[(ra + g + 8) * H_S + kg + q]);
                    a[mt][2] = fbits(h1s[(ra + g) * H_S + kg + q + 4]);
                    a[mt][3] = fbits(h1s[(ra + g + 8) * H_S + kg + q + 4]);
                }
#pragma unroll
                for (int nt = 0; nt < 4; nt++) {
                    uint32_t b[2] = {fbits(wb[(kl + q) * BB_S + nt * 8 + g]),
                                     fbits(wb[(kl + q + 4) * BB_S + nt * 8 + g])};
                    mma8(acc[0][nt], a[0], b, acc[0][nt]);
                    mma8(acc[1][nt], a[1], b, acc[1][nt]);
                }
            }
            // prefetch chunk c+3 into buffer (c+3)&3 == (c-1)&3: both warps of the
            // pair finished reading that buffer before this chunk's barrier.
            if (wm == 0 && c + 3 < 16)
                prefetch_w2(bwn + ((c + 3) & 3) * (16 * BB_S), W2, c + 3, cbase, lane);
        }
        // epilogue -> h2s
#pragma unroll
        for (int mt = 0; mt < 2; mt++) {
            int rr = rbase + mt * 16;
#pragma unroll
            for (int nt = 0; nt < 4; nt++) {
                int cc = cbase + nt * 8;
                h2s[(rr + g) * H_S + cc + 2 * q]     = silu_f(acc[mt][nt][0] + b2s[cc + 2 * q]);
                h2s[(rr + g) * H_S + cc + 2 * q + 1] = silu_f(acc[mt][nt][1] + b2s[cc + 2 * q + 1]);
                h2s[(rr + g + 8) * H_S + cc + 2 * q]     = silu_f(acc[mt][nt][2] + b2s[cc + 2 * q]);
                h2s[(rr + g + 8) * H_S + cc + 2 * q + 1] = silu_f(acc[mt][nt][3] + b2s[cc + 2 * q + 1]);
            }
        }
    }
    __syncthreads();

    // stage W3 from registers into (now dead) bb region, stride 24 (conflict-free)
    float* w3s = bb;
#pragma unroll
    for (int i = 0; i < 8; i++) {
        int idx = tid + i * 512;
        w3s[(idx >> 4) * W3_S + (idx & 15)] = w3reg[i];
    }
    __syncthreads();

    // ================= GEMM3: h = h2 @ W3 (K split 8-ways over warps) ======
    float* hpart = h1s;  // [8][64][20], h1s dead
    {
        int wm3 = wid & 1, wk = wid >> 1;  // wk in 0..7: K slice of 32
        int rb3 = wm3 * 32;
        float acc[2][2][4] = {};
#pragma unroll
        for (int ks = 0; ks < 4; ks++) {
            int k = wk * 32 + ks * 8;
            uint32_t a[2][4];
#pragma unroll
            for (int mt = 0; mt < 2; mt++) {
                int ra = rb3 + mt * 16;
                a[mt][0] = fbits(h2s[(ra + g) * H_S + k + q]);
                a[mt][1] = fbits(h2s[(ra + g + 8) * H_S + k + q]);
                a[mt][2] = fbits(h2s[(ra + g) * H_S + k + q + 4]);
                a[mt][3] = fbits(h2s[(ra + g + 8) * H_S + k + q + 4]);
            }
#pragma unroll
            for (int nt = 0; nt < 2; nt++) {
                uint32_t b[2] = {fbits(w3s[(k + q) * W3_S + nt * 8 + g]),
                                 fbits(w3s[(k + q + 4) * W3_S + nt * 8 + g])};
                mma8(acc[0][nt], a[0], b, acc[0][nt]);
                mma8(acc[1][nt], a[1], b, acc[1][nt]);
            }
        }
#pragma unroll
        for (int mt = 0; mt < 2; mt++) {
            int rr = rb3 + mt * 16;
#pragma unroll
            for (int nt = 0; nt < 2; nt++) {
                int cc = nt * 8;
                hpart[wk * 1280 + (rr + g) * 20 + cc + 2 * q]         = acc[mt][nt][0];
                hpart[wk * 1280 + (rr + g) * 20 + cc + 2 * q + 1]     = acc[mt][nt][1];
                hpart[wk * 1280 + (rr + g + 8) * 20 + cc + 2 * q]     = acc[mt][nt][2];
                hpart[wk * 1280 + (rr + g + 8) * 20 + cc + 2 * q + 1] = acc[mt][nt][3];
            }
        }
    }
    __syncthreads();

    // ================= per-row epilogue =================
    if (tid < 64) {
        int row = tid;
        float s[16];
        float fro2 = 0.f;
#pragma unroll
        for (int r = 0; r < 16; r++) {
            float v = b3s[r];
#pragma unroll
            for (int p = 0; p < 8; p++) v += hpart[p * 1280 + row * 20 + r];
            float sr = 2.f / (1.f + __expf(-v));
            s[r] = sr;
            fro2 += sr * sr * cn2s[r];
        }
        float fro = sqrtf(fro2);
        // cap = 0.5 * 0.1 * sqrt(128*16)
        float scale = fminf(2.2627416997969522f / fmaxf(fro, 1e-9f), 1.f);

        float v = dt_norm_g[r0 + row];
        if (isnan(v)) v = 0.f;
        v = fminf(fmaxf(v, 0.f), 1.f);
        float logdt = fminf(-3.f + v * 11.f, 2.7781512503836436f);  // log10(600)
        float dt = fmaxf(expf(logdt * 2.302585092994046f), 1e-30f);
        float lamg = expf(-0.1f * dt);
        g_lamg[r0 + row] = lamg;
#pragma unroll
        for (int r = 0; r < 16; r++) {
            float ss = s[r] * scale;
            float lp = expf(-ss * ss * dt) * lamg;
            g_d[(size_t)(r0 + row) * 16 + r] = lp - lamg;
        }
    }
}

// ============================================================================
// Kernel 2: z_next = lam_g*z + ((lam_para - lam_g) .* (z@U)) @ U^T
// Direct register->global epilogue (no smem RMW, no stage-out pass).
// ============================================================================
__global__ void __launch_bounds__(256, 3) dyn_kernel(
    const float* __restrict__ z, const float* __restrict__ U,
    float* __restrict__ out) {
    extern __shared__ float sm2[];
    float* zs = sm2;            // 64*132 = 8448
    float* Us = sm2 + 8448;     // 128*24 = 3072 (U[j][r] at j*24+r)
    float* Ut = sm2 + 11520;    // 16*136 = 2176 (U^T[r][j] at r*136+j)
    float* cs = sm2 + 13696;    // 64*20  = 1280
    float* lg = sm2 + 14976;    // 64
    // total 15040 floats = 60160 B

    const int tid = threadIdx.x;
    const int wid = tid >> 5, lane = tid & 31;
    const int g = lane >> 2, q = lane & 3;
    const int r0 = blockIdx.x * MTILE;

    // --- stage z (nan0, float4) ---
#pragma unroll
    for (int i = 0; i < 8; i++) {
        int idx = tid + i * 256;                    // < 2048 float4s
        int row = idx >> 5, c4 = (idx & 31) << 2;
        float4 v = *reinterpret_cast<const float4*>(&z[(size_t)(r0 + row) * ZD + c4]);
        v.x = nan0(v.x); v.y = nan0(v.y); v.z = nan0(v.z); v.w = nan0(v.w);
        *reinterpret_cast<float4*>(&zs[row * 132 + c4]) = v;
    }
    // --- stage U both layouts ---
#pragma unroll
    for (int i = 0; i < 8; i++) {
        int idx = tid + i * 256;                    // < 2048
        int j = idx >> 4, r = idx & 15;
        float v = nan0(U[j * RR + r]);
        Us[j * 24 + r] = v;
        Ut[r * 136 + j] = v;
    }
    if (tid < 64) lg[tid] = g_lamg[r0 + tid];
    __syncthreads();

    // ===== GEMM A: cs[row][r] = d[row][r] * (z @ U)[row][r] =====
    {
        int mt = wid >> 1, nt = wid & 1;
        int rbase = mt * 16, cbase = nt * 8;
        float acc[4] = {0.f, 0.f, 0.f, 0.f};
#pragma unroll
        for (int k = 0; k < 16; k++) {
            int k0 = k * 8;
            uint32_t a[4] = {
                fbits(zs[(rbase + g) * 132 + k0 + q]),
                fbits(zs[(rbase + g + 8) * 132 + k0 + q]),
                fbits(zs[(rbase + g) * 132 + k0 + q + 4]),
                fbits(zs[(rbase + g + 8) * 132 + k0 + q + 4])};
            uint32_t b[2] = {fbits(Us[(k0 + q) * 24 + cbase + g]),
                             fbits(Us[(k0 + q + 4) * 24 + cbase + g])};
            mma8(acc, a, b, acc);
        }
        int row0 = rbase + g, row1 = rbase + g + 8;
        int c0 = cbase + 2 * q, c1 = c0 + 1;
        cs[row0 * 20 + c0] = acc[0] * g_d[(size_t)(r0 + row0) * 16 + c0];
        cs[row0 * 20 + c1] = acc[1] * g_d[(size_t)(r0 + row0) * 16 + c1];
        cs[row1 * 20 + c0] = acc[2] * g_d[(size_t)(r0 + row1) * 16 + c0];
        cs[row1 * 20 + c1] = acc[3] * g_d[(size_t)(r0 + row1) * 16 + c1];
    }
    __syncthreads();

    // ===== GEMM B + identity, direct to global =====
    {
        int wm = wid >> 1, wn = wid & 1;
        int rbase = wm * 16;
        float acc[8][4];
#pragma unroll
        for (int nt = 0; nt < 8; nt++)
#pragma unroll
            for (int i = 0; i < 4; i++) acc[nt][i] = 0.f;
#pragma unroll
        for (int ks = 0; ks < 2; ks++) {
            int k0 = ks * 8;
            uint32_t a[4] = {
                fbits(cs[(rbase + g) * 20 + k0 + q]),
                fbits(cs[(rbase + g + 8) * 20 + k0 + q]),
                fbits(cs[(rbase + g) * 20 + k0 + q + 4]),
                fbits(cs[(rbase + g + 8) * 20 + k0 + q + 4])};
#pragma unroll
            for (int nt = 0; nt < 8; nt++) {
                int cb = (wn * 8 + nt) * 8;
                uint32_t b[2] = {fbits(Ut[(k0 + q) * 136 + cb + g]),
                                 fbits(Ut[(k0 + q + 4) * 136 + cb + g])};
                mma8(acc[nt], a, b, acc[nt]);
            }
        }
        int row0 = rbase + g, row1 = rbase + g + 8;
        float l0 = lg[row0], l1 = lg[row1];
        size_t gr0 = (size_t)(r0 + row0) * ZD, gr1 = (size_t)(r0 + row1) * ZD;
#pragma unroll
        for (int nt = 0; nt < 8; nt++) {
            int cb = (wn * 8 + nt) * 8;
            int c0 = cb + 2 * q;
            float2 z0 = *reinterpret_cast<const float2*>(&zs[row0 * 132 + c0]);
            float2 o0;
            o0.x = l0 * z0.x + acc[nt][0];
            o0.y = l0 * z0.y + acc[nt][1];
            *reinterpret_cast<float2*>(&out[gr0 + c0]) = o0;
            float2 z1 = *reinterpret_cast<const float2*>(&zs[row1 * 132 + c0]);
            float2 o1;
            o1.x = l1 * z1.x + acc[nt][2];
            o1.y = l1 * z1.y + acc[nt][3];
            *reinterpret_cast<float2*>(&out[gr1 + c0]) = o1;
        }
    }
}

extern "C" void kernel_launch(void* const* d_in, const int* in_sizes, int n_in,
                              void* d_out, int out_size) {
    const float* pt      = (const float*)d_in[0];
    const float* z       = (const float*)d_in[1];
    const float* dt_norm = (const float*)d_in[2];
    const float* base_U  = (const float*)d_in[3];
    const float* W1      = (const float*)d_in[4];
    const float* b1      = (const float*)d_in[5];
    const float* W2      = (const float*)d_in[6];
    const float* b2      = (const float*)d_in[7];
    const float* W3      = (const float*)d_in[8];
    const float* b3      = (const float*)d_in[9];
    float* out = (float*)d_out;

    cudaFuncSetAttribute(mlp_kernel, cudaFuncAttributeMaxDynamicSharedMemorySize, 228864);
    cudaFuncSetAttribute(dyn_kernel, cudaFuncAttributeMaxDynamicSharedMemorySize, 60160);

    mlp_kernel<<<NBLK, 512, 228864>>>(pt, dt_norm, base_U, W1, b1, W2, b2, W3, b3);
    dyn_kernel<<<NBLK, 256, 60160>>>(z, base_U, out);
}

// round 6
// speedup vs baseline: 1.1188x; 1.1188x over previous
#include <cuda_runtime.h>
#include <cstdint>
#include <math.h>

#define BATCH 262144
#define GD 16
#define HID 256
#define RR 16
#define ZD 128
#define MTILE 64
#define NBLK (BATCH / MTILE)

// padded smem strides (floats)
#define XS_S 20
#define W1_S 264

// ---- smem float offsets (mlp kernel) ----
#define OFF_XS    0        // 64*20      = 1280
#define OFF_W1    1280     // 16*264     = 4224
#define OFF_H1F   5504     // 16384 (64KB)  [hpart overlays later]
#define OFF_W3F   21888    // 4096  (16KB)
#define OFF_RING  25984    // 3*8192 = 24576 (3x32KB) [h2frag overlays later]
#define SMEM_FLOATS 50560  // 202240 bytes

// scratch between kernels (device globals: allocation-free)
__device__ float g_lamg[BATCH];
__device__ float g_d[BATCH * RR];
// fragment-major weight images: W2 frags (65536 f) @0, W3 frags (4096 f) @65536
__device__ __align__(256) float g_wsw[69632];

__device__ __forceinline__ uint32_t fbits(float x) { return __float_as_uint(x); }
__device__ __forceinline__ float nan0(float v) { return isfinite(v) ? v : 0.f; }
__device__ __forceinline__ float silu_f(float x) { return x * (1.f / (1.f + __expf(-x))); }

__device__ __forceinline__ uint32_t smem_u32(const void* p) {
    uint32_t a;
    asm("{ .reg .u64 t; cvta.to.shared.u64 t, %1; cvt.u32.u64 %0, t; }" : "=r"(a) : "l"(p));
    return a;
}
__device__ __forceinline__ void cpa16(uint32_t saddr, const void* g) {
    asm volatile("cp.async.cg.shared.global [%0], [%1], 16;\n" ::"r"(saddr), "l"(g));
}
__device__ __forceinline__ void cpcommit() { asm volatile("cp.async.commit_group;\n"); }
template <int N>
__device__ __forceinline__ void cpwait() { asm volatile("cp.async.wait_group %0;\n" ::"n"(N)); }

__device__ __forceinline__ void mma8(float d[4], const uint32_t a[4],
                                     const uint32_t b[2], const float c[4]) {
    asm volatile(
        "mma.sync.aligned.m16n8k8.row.col.f32.tf32.tf32.f32 "
        "{%0,%1,%2,%3}, {%4,%5,%6,%7}, {%8,%9}, {%10,%11,%12,%13};\n"
        : "=f"(d[0]), "=f"(d[1]), "=f"(d[2]), "=f"(d[3])
        : "r"(a[0]), "r"(a[1]), "r"(a[2]), "r"(a[3]),
          "r"(b[0]), "r"(b[1]),
          "f"(c[0]), "f"(c[1]), "f"(c[2]), "f"(c[3]));
}

// scatter-store a D-fragment tile (v0..v3) into A-fragment-major layout:
// frag[rb][ks][lane] float4 = {(g,q),(g+8,q),(g,q+4),(g+8,q+4)}
__device__ __forceinline__ void frag_store(float* frag, int rb, int ks, int g, int q,
                                           float v0, float v1, float v2, float v3) {
    int q2 = q << 1;
    int hi = (q2 >> 2) << 1;   // 0 or 2 (element offset within float4)
    int qp = q2 & 3;
    float* p = frag + ((rb * 32 + ks) * 32 + (g * 4 + qp)) * 4 + hi;
    *reinterpret_cast<float2*>(p) = make_float2(v0, v2);
    *reinterpret_cast<float2*>(p + 4) = make_float2(v1, v3);
}

// ============================================================================
// Kernel 0: build fragment-major W2 / W3 images
// W2 frag: [chunk8][ks4][wn8][nt4][lane32] float2 = {W2[kb+q][col], W2[kb+q+4][col]}
//   kb = chunk*32+ks*8, col = wn*32+nt*8+g, lane = g*4+q
// W3 frag: [ks32][nt2][lane32] float2 = {W3[ks*8+q][nt*8+g], W3[ks*8+q+4][nt*8+g]}
// ============================================================================
__global__ void prep_kernel(const float* __restrict__ W2, const float* __restrict__ W3) {
    int idx = blockIdx.x * 256 + threadIdx.x;
    if (idx < 65536) {
        int k = idx >> 8, n = idx & 255;
        int chunk = k >> 5, km = k & 31;
        int ks = km >> 3, r = km & 7;
        int q = r & 3, pair = r >> 2;
        int wn = n >> 5, nt = (n >> 3) & 3, g = n & 7;
        int f2 = chunk * 4096 + ((ks * 8 + wn) * 4 + nt) * 32 + g * 4 + q;
        g_wsw[f2 * 2 + pair] = W2[idx];
    } else if (idx < 69632) {
        int t = idx - 65536;
        int k = t >> 4, n = t & 15;
        int ks = k >> 3, r = k & 7;
        int q = r & 3, pair = r >> 2;
        int nt = n >> 3, g = n & 7;
        int f2 = (ks * 2 + nt) * 32 + g * 4 + q;
        g_wsw[65536 + f2 * 2 + pair] = W3[t];
    }
}

// ============================================================================
// Kernel 1: fused MLP  pt -> (lam_g, d[r] = lam_para[r] - lam_g)
// 512 threads, 64 rows/CTA. Fragment-major operands: 1 LDS.128 per A-frag,
// 1 LDS.64 per B-frag. W2 streamed through 3-slot ring of pre-built fragments.
// ============================================================================
__global__ void __launch_bounds__(512, 1) mlp_kernel(
    const float* __restrict__ pt, const float* __restrict__ dt_norm_g,
    const float* __restrict__ U,
    const float* __restrict__ W1, const float* __restrict__ b1,
    const float* __restrict__ b2, const float* __restrict__ b3) {
    extern __shared__ float sm[];
    float* xs  = sm + OFF_XS;
    float* w1s = sm + OFF_W1;
    float* h1f = sm + OFF_H1F;
    float* w3f = sm + OFF_W3F;
    float* ring = sm + OFF_RING;
    float* h2f = sm + OFF_RING;    // overlays ring after GEMM2
    float* hp  = sm + OFF_H1F;     // hpart overlays h1frag in GEMM3

    __shared__ float b1s[256], b2s[256], b3s[16], cn2s[16];

    const int tid = threadIdx.x;
    const int wid = tid >> 5, lane = tid & 31;
    const int g = lane >> 2, q = lane & 3;
    const int r0 = blockIdx.x * MTILE;
    const uint32_t sb = smem_u32(sm);
    const char* gw = (const char*)g_wsw;

    // --- cp.async staging: w3 frags (group0), W2 chunks 0,1 (groups 1,2) ---
#pragma unroll
    for (int i = 0; i < 2; i++) {
        int idx = tid + i * 512;                // 1024 float4
        cpa16(sb + OFF_W3F * 4 + idx * 16, gw + 65536 * 4 + idx * 16);
    }
    cpcommit();
#pragma unroll
    for (int c = 0; c < 2; c++) {
#pragma unroll
        for (int i = 0; i < 4; i++) {
            int idx = tid + i * 512;            // 2048 float4 per chunk
            cpa16(sb + (OFF_RING + c * 8192) * 4 + idx * 16, gw + c * 32768 + idx * 16);
        }
        cpcommit();
    }

    // --- stage x (nan0) + W1 (plain) ---
#pragma unroll
    for (int i = 0; i < 2; i++) {
        int idx = tid + i * 512;                // < 1024
        int rr = idx >> 4, cc = idx & 15;
        xs[rr * XS_S + cc] = nan0(pt[(size_t)(r0 + rr) * GD + cc]);
    }
#pragma unroll
    for (int i = 0; i < 8; i++) {
        int idx = tid + i * 512;                // < 4096
        w1s[(idx >> 8) * W1_S + (idx & 255)] = W1[idx];
    }
    if (tid < 256) {
        b1s[tid] = b1[tid];
        b2s[tid] = b2[tid];
    }
    if (tid < 16) {
        b3s[tid] = b3[tid];
        float s = 0.f;
        for (int j = 0; j < ZD; j++) {
            float u = nan0(U[j * RR + tid]);
            s += u * u;
        }
        cn2s[tid] = s;
    }
    __syncthreads();

    // warp tiling GEMM1/GEMM2: 2 x 8 warps, each 32 rows x 32 cols
    const int wm = wid >> 3, wn = wid & 7;
    const int rbase = wm * 32, cbase = wn * 32;

    // ================= GEMM1: h1 = silu(x @ W1 + b1) -> h1frag =============
    {
#pragma unroll
        for (int mt = 0; mt < 2; mt++) {
#pragma unroll
            for (int nt = 0; nt < 4; nt++) {
                float acc[4] = {0.f, 0.f, 0.f, 0.f};
#pragma unroll
                for (int ks = 0; ks < 2; ks++) {
                    int k0 = ks * 8;
                    int ra = rbase + mt * 16;
                    uint32_t a[4] = {
                        fbits(xs[(ra + g) * XS_S + k0 + q]),
                        fbits(xs[(ra + g + 8) * XS_S + k0 + q]),
                        fbits(xs[(ra + g) * XS_S + k0 + q + 4]),
                        fbits(xs[(ra + g + 8) * XS_S + k0 + q + 4])};
                    int cb = cbase + nt * 8;
                    uint32_t b[2] = {fbits(w1s[(k0 + q) * W1_S + cb + g]),
                                     fbits(w1s[(k0 + q + 4) * W1_S + cb + g])};
                    mma8(acc, a, b, acc);
                }
                int cc = cbase + nt * 8;
                float s0 = silu_f(acc[0] + b1s[cc + 2 * q]);
                float s1 = silu_f(acc[1] + b1s[cc + 2 * q + 1]);
                float s2 = silu_f(acc[2] + b1s[cc + 2 * q]);
                float s3 = silu_f(acc[3] + b1s[cc + 2 * q + 1]);
                frag_store(h1f, wm * 2 + mt, wn * 4 + nt, g, q, s0, s1, s2, s3);
            }
        }
    }
    __syncthreads();

    // ================= GEMM2: h2 = silu(h1 @ W2 + b2) ======================
    float acc[2][4][4];
#pragma unroll
    for (int mt = 0; mt < 2; mt++)
#pragma unroll
        for (int nt = 0; nt < 4; nt++)
#pragma unroll
            for (int i = 0; i < 4; i++) acc[mt][nt][i] = 0.f;

    for (int c = 0; c < 8; c++) {
        if (c == 7) cpwait<0>(); else cpwait<1>();
        __syncthreads();
        if (c + 2 < 8) {
            int j = c + 2;
            int slot = j - (j / 3) * 3;
#pragma unroll
            for (int i = 0; i < 4; i++) {
                int idx = tid + i * 512;
                cpa16(sb + (OFF_RING + slot * 8192) * 4 + idx * 16,
                      gw + (size_t)j * 32768 + idx * 16);
            }
            cpcommit();
        }
        const float* wb = ring + (c - (c / 3) * 3) * 8192;
#pragma unroll
        for (int ks = 0; ks < 4; ks++) {
            int kk = c * 4 + ks;
            uint4 a0 = *reinterpret_cast<const uint4*>(&h1f[(((wm * 2 + 0) * 32 + kk) * 32 + lane) * 4]);
            uint4 a1 = *reinterpret_cast<const uint4*>(&h1f[(((wm * 2 + 1) * 32 + kk) * 32 + lane) * 4]);
            uint32_t A0[4] = {a0.x, a0.y, a0.z, a0.w};
            uint32_t A1[4] = {a1.x, a1.y, a1.z, a1.w};
#pragma unroll
            for (int nt = 0; nt < 4; nt++) {
                uint2 bv = *reinterpret_cast<const uint2*>(&wb[(((ks * 8 + wn) * 4 + nt) * 32 + lane) * 2]);
                uint32_t B[2] = {bv.x, bv.y};
                mma8(acc[0][nt], A0, B, acc[0][nt]);
                mma8(acc[1][nt], A1, B, acc[1][nt]);
            }
        }
    }
    __syncthreads();   // all warps done with ring before h2frag overlays it

    // epilogue -> h2frag
#pragma unroll
    for (int mt = 0; mt < 2; mt++) {
#pragma unroll
        for (int nt = 0; nt < 4; nt++) {
            int cc = cbase + nt * 8;
            float s0 = silu_f(acc[mt][nt][0] + b2s[cc + 2 * q]);
            float s1 = silu_f(acc[mt][nt][1] + b2s[cc + 2 * q + 1]);
            float s2 = silu_f(acc[mt][nt][2] + b2s[cc + 2 * q]);
            float s3 = silu_f(acc[mt][nt][3] + b2s[cc + 2 * q + 1]);
            frag_store(h2f, wm * 2 + mt, wn * 4 + nt, g, q, s0, s1, s2, s3);
        }
    }
    __syncthreads();

    // ================= GEMM3: h = h2 @ W3 (K split 8-ways) =================
    {
        int wm3 = wid & 1, wk = wid >> 1;
        float a3[2][2][4] = {};
#pragma unroll
        for (int ksl = 0; ksl < 4; ksl++) {
            int kk = wk * 4 + ksl;
            uint4 a0 = *reinterpret_cast<const uint4*>(&h2f[(((wm3 * 2 + 0) * 32 + kk) * 32 + lane) * 4]);
            uint4 a1 = *reinterpret_cast<const uint4*>(&h2f[(((wm3 * 2 + 1) * 32 + kk) * 32 + lane) * 4]);
            uint32_t A0[4] = {a0.x, a0.y, a0.z, a0.w};
            uint32_t A1[4] = {a1.x, a1.y, a1.z, a1.w};
#pragma unroll
            for (int nt3 = 0; nt3 < 2; nt3++) {
                uint2 bv = *reinterpret_cast<const uint2*>(&w3f[((kk * 2 + nt3) * 32 + lane) * 2]);
                uint32_t B[2] = {bv.x, bv.y};
                mma8(a3[0][nt3], A0, B, a3[0][nt3]);
                mma8(a3[1][nt3], A1, B, a3[1][nt3]);
            }
        }
        // stash partials for cross-K reduction (hpart overlays dead h1frag)
#pragma unroll
        for (int mt = 0; mt < 2; mt++) {
            int rr = wm3 * 32 + mt * 16;
#pragma unroll
            for (int nt3 = 0; nt3 < 2; nt3++) {
                int cc = nt3 * 8;
                hp[wk * 1280 + (rr + g) * 20 + cc + 2 * q]         = a3[mt][nt3][0];
                hp[wk * 1280 + (rr + g) * 20 + cc + 2 * q + 1]     = a3[mt][nt3][1];
                hp[wk * 1280 + (rr + g + 8) * 20 + cc + 2 * q]     = a3[mt][nt3][2];
                hp[wk * 1280 + (rr + g + 8) * 20 + cc + 2 * q + 1] = a3[mt][nt3][3];
            }
        }
    }
    __syncthreads();

    // ================= per-row epilogue =================
    if (tid < 64) {
        int row = tid;
        float s[16], fro2 = 0.f;
#pragma unroll
        for (int r = 0; r < 16; r++) {
            float v = b3s[r];
#pragma unroll
            for (int p = 0; p < 8; p++) v += hp[p * 1280 + row * 20 + r];
            float sr = 2.f / (1.f + __expf(-v));
            s[r] = sr;
            fro2 += sr * sr * cn2s[r];
        }
        float fro = sqrtf(fro2);
        float scale = fminf(2.2627416997969522f / fmaxf(fro, 1e-9f), 1.f);  // cap

        float v = dt_norm_g[r0 + row];
        if (isnan(v)) v = 0.f;
        v = fminf(fmaxf(v, 0.f), 1.f);
        float logdt = fminf(-3.f + v * 11.f, 2.7781512503836436f);          // log10(600)
        float dt = fmaxf(expf(logdt * 2.302585092994046f), 1e-30f);
        float lamg = expf(-0.1f * dt);
        g_lamg[r0 + row] = lamg;
#pragma unroll
        for (int r = 0; r < 16; r++) {
            float ss = s[r] * scale;
            float lp = expf(-ss * ss * dt) * lamg;
            g_d[(size_t)(r0 + row) * 16 + r] = lp - lamg;
        }
    }
}

// ============================================================================
// Kernel 2: z_next = lam_g*z + ((lam_para - lam_g) .* (z@U)) @ U^T
// (R4 best: direct register->global epilogue)
// ============================================================================
__global__ void __launch_bounds__(256, 3) dyn_kernel(
    const float* __restrict__ z, const float* __restrict__ U,
    float* __restrict__ out) {
    extern __shared__ float sm2[];
    float* zs = sm2;            // 64*132 = 8448
    float* Us = sm2 + 8448;     // 128*24 = 3072
    float* Ut = sm2 + 11520;    // 16*136 = 2176
    float* cs = sm2 + 13696;    // 64*20  = 1280
    float* lg = sm2 + 14976;    // 64
    const int tid = threadIdx.x;
    const int wid = tid >> 5, lane = tid & 31;
    const int g = lane >> 2, q = lane & 3;
    const int r0 = blockIdx.x * MTILE;

#pragma unroll
    for (int i = 0; i < 8; i++) {
        int idx = tid + i * 256;
        int row = idx >> 5, c4 = (idx & 31) << 2;
        float4 v = *reinterpret_cast<const float4*>(&z[(size_t)(r0 + row) * ZD + c4]);
        v.x = nan0(v.x); v.y = nan0(v.y); v.z = nan0(v.z); v.w = nan0(v.w);
        *reinterpret_cast<float4*>(&zs[row * 132 + c4]) = v;
    }
#pragma unroll
    for (int i = 0; i < 8; i++) {
        int idx = tid + i * 256;
        int j = idx >> 4, r = idx & 15;
        float v = nan0(U[j * RR + r]);
        Us[j * 24 + r] = v;
        Ut[r * 136 + j] = v;
    }
    if (tid < 64) lg[tid] = g_lamg[r0 + tid];
    __syncthreads();

    {
        int mt = wid >> 1, nt = wid & 1;
        int rbase = mt * 16, cbase = nt * 8;
        float acc[4] = {0.f, 0.f, 0.f, 0.f};
#pragma unroll
        for (int k = 0; k < 16; k++) {
            int k0 = k * 8;
            uint32_t a[4] = {
                fbits(zs[(rbase + g) * 132 + k0 + q]),
                fbits(zs[(rbase + g + 8) * 132 + k0 + q]),
                fbits(zs[(rbase + g) * 132 + k0 + q + 4]),
                fbits(zs[(rbase + g + 8) * 132 + k0 + q + 4])};
            uint32_t b[2] = {fbits(Us[(k0 + q) * 24 + cbase + g]),
                             fbits(Us[(k0 + q + 4) * 24 + cbase + g])};
            mma8(acc, a, b, acc);
        }
        int row0 = rbase + g, row1 = rbase + g + 8;
        int c0 = cbase + 2 * q, c1 = c0 + 1;
        cs[row0 * 20 + c0] = acc[0] * g_d[(size_t)(r0 + row0) * 16 + c0];
        cs[row0 * 20 + c1] = acc[1] * g_d[(size_t)(r0 + row0) * 16 + c1];
        cs[row1 * 20 + c0] = acc[2] * g_d[(size_t)(r0 + row1) * 16 + c0];
        cs[row1 * 20 + c1] = acc[3] * g_d[(size_t)(r0 + row1) * 16 + c1];
    }
    __syncthreads();

    {
        int wm = wid >> 1, wn = wid & 1;
        int rbase = wm * 16;
        float acc[8][4];
#pragma unroll
        for (int nt = 0; nt < 8; nt++)
#pragma unroll
            for (int i = 0; i < 4; i++) acc[nt][i] = 0.f;
#pragma unroll
        for (int ks = 0; ks < 2; ks++) {
            int k0 = ks * 8;
            uint32_t a[4] = {
                fbits(cs[(rbase + g) * 20 + k0 + q]),
                fbits(cs[(rbase + g + 8) * 20 + k0 + q]),
                fbits(cs[(rbase + g) * 20 + k0 + q + 4]),
                fbits(cs[(rbase + g + 8) * 20 + k0 + q + 4])};
#pragma unroll
            for (int nt = 0; nt < 8; nt++) {
                int cb = (wn * 8 + nt) * 8;
                uint32_t b[2] = {fbits(Ut[(k0 + q) * 136 + cb + g]),
                                 fbits(Ut[(k0 + q + 4) * 136 + cb + g])};
                mma8(acc[nt], a, b, acc[nt]);
            }
        }
        int row0 = rbase + g, row1 = rbase + g + 8;
        float l0 = lg[row0], l1 = lg[row1];
        size_t gr0 = (size_t)(r0 + row0) * ZD, gr1 = (size_t)(r0 + row1) * ZD;
#pragma unroll
        for (int nt = 0; nt < 8; nt++) {
            int cb = (wn * 8 + nt) * 8;
            int c0 = cb + 2 * q;
            float2 z0 = *reinterpret_cast<const float2*>(&zs[row0 * 132 + c0]);
            float2 o0;
            o0.x = l0 * z0.x + acc[nt][0];
            o0.y = l0 * z0.y + acc[nt][1];
            *reinterpret_cast<float2*>(&out[gr0 + c0]) = o0;
            float2 z1 = *reinterpret_cast<const float2*>(&zs[row1 * 132 + c0]);
            float2 o1;
            o1.x = l1 * z1.x + acc[nt][2];
            o1.y = l1 * z1.y + acc[nt][3];
            *reinterpret_cast<float2*>(&out[gr1 + c0]) = o1;
        }
    }
}

extern "C" void kernel_launch(void* const* d_in, const int* in_sizes, int n_in,
                              void* d_out, int out_size) {
    const float* pt      = (const float*)d_in[0];
    const float* z       = (const float*)d_in[1];
    const float* dt_norm = (const float*)d_in[2];
    const float* base_U  = (const float*)d_in[3];
    const float* W1      = (const float*)d_in[4];
    const float* b1      = (const float*)d_in[5];
    const float* W2      = (const float*)d_in[6];
    const float* b2      = (const float*)d_in[7];
    const float* W3      = (const float*)d_in[8];
    const float* b3      = (const float*)d_in[9];
    float* out = (float*)d_out;

    cudaFuncSetAttribute(mlp_kernel, cudaFuncAttributeMaxDynamicSharedMemorySize,
                         SMEM_FLOATS * 4);
    cudaFuncSetAttribute(dyn_kernel, cudaFuncAttributeMaxDynamicSharedMemorySize, 60160);

    prep_kernel<<<272, 256>>>(W2, W3);
    mlp_kernel<<<NBLK, 512, SMEM_FLOATS * 4>>>(pt, dt_norm, base_U, W1, b1, b2, b3);
    dyn_kernel<<<NBLK, 256, 60160>>>(z, base_U, out);
}

// round 7
// speedup vs baseline: 2.1117x; 1.8875x over previous
#include <cuda_runtime.h>
#include <cuda_fp16.h>
#include <cstdint>
#include <math.h>

#define BATCH 262144
#define GD 16
#define HID 256
#define RR 16
#define ZD 128
#define MTILE 64
#define NBLK (BATCH / MTILE)

// ---- mlp dynamic smem layout (bytes) ----
#define OFF_XF   0        // x A-frags: 4rb x 1kk x 32lane x 16B = 2048
#define OFF_W1F  2048     // W1 B-frags: 1024 slots x 8B = 8192
#define OFF_W3F  10240    // W3 B-frags: 1024 slots x 8B = 8192
#define OFF_H1F  18432    // h1 A-frags 32768 (h2 frags overlay after GEMM2)
#define OFF_RING 51200    // W2 ring 2 x 16384 = 32768 (GEMM3 partials overlay)
#define SMEM_BYTES 83968

// scratch (device globals: allocation-free)
__device__ float g_lamg[BATCH];
__device__ float g_d[BATCH * RR];
// fp16 fragment images: W2 8 chunks x 16KB @u32 0, W1 @u32 32768, W3 @u32 34816
__device__ __align__(256) uint32_t g_wfrag[36864];

__device__ __forceinline__ uint32_t fbits(float x) { return __float_as_uint(x); }
__device__ __forceinline__ float nan0(float v) { return isfinite(v) ? v : 0.f; }
__device__ __forceinline__ float silu_f(float x) { return x * (1.f / (1.f + __expf(-x))); }
__device__ __forceinline__ uint32_t packh(float lo, float hi) {
    uint32_t u;
    asm("cvt.rn.f16x2.f32 %0, %1, %2;" : "=r"(u) : "f"(hi), "f"(lo));
    return u;
}
__device__ __forceinline__ uint32_t smem_u32(const void* p) {
    uint32_t a;
    asm("{ .reg .u64 t; cvta.to.shared.u64 t, %1; cvt.u32.u64 %0, t; }" : "=r"(a) : "l"(p));
    return a;
}
__device__ __forceinline__ void cpa16(uint32_t saddr, const void* g) {
    asm volatile("cp.async.cg.shared.global [%0], [%1], 16;\n" ::"r"(saddr), "l"(g));
}
__device__ __forceinline__ void cpcommit() { asm volatile("cp.async.commit_group;\n"); }
template <int N>
__device__ __forceinline__ void cpwait() { asm volatile("cp.async.wait_group %0;\n" ::"n"(N)); }

// fp16 mma m16n8k16, fp32 accumulate
__device__ __forceinline__ void mma16(float d[4], const uint32_t a[4],
                                      const uint32_t b[2], const float c[4]) {
    asm volatile(
        "mma.sync.aligned.m16n8k16.row.col.f32.f16.f16.f32 "
        "{%0,%1,%2,%3}, {%4,%5,%6,%7}, {%8,%9}, {%10,%11,%12,%13};\n"
        : "=f"(d[0]), "=f"(d[1]), "=f"(d[2]), "=f"(d[3])
        : "r"(a[0]), "r"(a[1]), "r"(a[2]), "r"(a[3]),
          "r"(b[0]), "r"(b[1]),
          "f"(c[0]), "f"(c[1]), "f"(c[2]), "f"(c[3]));
}
// tf32 mma m16n8k8 (dyn kernel)
__device__ __forceinline__ void mma8(float d[4], const uint32_t a[4],
                                     const uint32_t b[2], const float c[4]) {
    asm volatile(
        "mma.sync.aligned.m16n8k8.row.col.f32.tf32.tf32.f32 "
        "{%0,%1,%2,%3}, {%4,%5,%6,%7}, {%8,%9}, {%10,%11,%12,%13};\n"
        : "=f"(d[0]), "=f"(d[1]), "=f"(d[2]), "=f"(d[3])
        : "r"(a[0]), "r"(a[1]), "r"(a[2]), "r"(a[3]),
          "r"(b[0]), "r"(b[1]),
          "f"(c[0]), "f"(c[1]), "f"(c[2]), "f"(c[3]));
}

// ============================================================================
// Kernel 0: build fp16 B-fragment images.
// B-frag (m16n8k16, col n = groupID g, rows k): b0 = {B[2q][n],B[2q+1][n]},
// b1 = {B[2q+8][n],B[2q+9][n]}; lane = g*4+q; uint2 halfs order
// [b0.lo,b0.hi,b1.lo,b1.hi] -> half_idx = slot*4 + (k8>=8)*2 + (k&1).
// ============================================================================
__global__ void prep_kernel(const float* __restrict__ W1, const float* __restrict__ W2,
                            const float* __restrict__ W3) {
    __half* gh = (__half*)g_wfrag;
    int idx = blockIdx.x * 256 + threadIdx.x;
    if (idx < 65536) {                    // W2 [256k x 256n]
        int k = idx >> 8, n = idx & 255;
        int chunk = k >> 5, ks = (k >> 4) & 1, kl = k & 15;
        int b_idx = kl >> 3, q = (kl & 7) >> 1, par = kl & 1;
        int wn = n >> 5, nt = (n >> 3) & 3, g = n & 7;
        int slot = chunk * 2048 + ((ks * 8 + wn) * 4 + nt) * 32 + g * 4 + q;
        gh[slot * 4 + b_idx * 2 + par] = __float2half_rn(W2[idx]);
    } else if (idx < 69632) {             // W1 [16k x 256n]
        int t = idx - 65536;
        int k = t >> 8, n = t & 255;
        int b_idx = k >> 3, q = (k & 7) >> 1, par = k & 1;
        int wn = n >> 5, nt = (n >> 3) & 3, g = n & 7;
        int slot = (wn * 4 + nt) * 32 + g * 4 + q;
        gh[65536 + slot * 4 + b_idx * 2 + par] = __float2half_rn(W1[t]);
    } else if (idx < 73728) {             // W3 [256k x 16n]
        int t = idx - 69632;
        int k = t >> 4, n = t & 15;
        int ks = k >> 4, kl = k & 15;
        int b_idx = kl >> 3, q = (kl & 7) >> 1, par = kl & 1;
        int nt = n >> 3, g = n & 7;
        int slot = (ks * 2 + nt) * 32 + g * 4 + q;
        gh[69632 + slot * 4 + b_idx * 2 + par] = __float2half_rn(W3[t]);
    }
}

// ============================================================================
// Kernel 1: fused MLP, fp16 mma, 64 rows/CTA, 512 threads, 2 CTAs/SM.
// ============================================================================
__global__ void __launch_bounds__(512, 2) mlp_kernel(
    const float* __restrict__ pt, const float* __restrict__ dt_norm_g,
    const float* __restrict__ U,
    const float* __restrict__ b1, const float* __restrict__ b2,
    const float* __restrict__ b3) {
    extern __shared__ char smc[];
    __shared__ float b1s[256], b2s[256], b3s[16], cn2s[16];

    const int tid = threadIdx.x;
    const int wid = tid >> 5, lane = tid & 31;
    const int g = lane >> 2, q = lane & 3;
    const int r0 = blockIdx.x * MTILE;
    const uint32_t sb = smem_u32(smc);
    const char* gw = (const char*)g_wfrag;

    // group 0: W1 frags (8KB) + W3 frags (8KB)
    cpa16(sb + OFF_W1F + tid * 16, gw + 131072 + tid * 16);   // 512x16B = 8KB
    cpa16(sb + OFF_W3F + tid * 16, gw + 139264 + tid * 16);
    cpcommit();
    // group 1: W2 chunk 0
#pragma unroll
    for (int i = 0; i < 2; i++) {
        int idx = tid + i * 512;
        cpa16(sb + OFF_RING + idx * 16, gw + idx * 16);
    }
    cpcommit();

    // --- stage x as fp16 A-frags (nan0) ---
    __half* xf = (__half*)(smc + OFF_XF);
#pragma unroll
    for (int i = 0; i < 2; i++) {
        int idx = tid + i * 512;                 // 1024 elements
        int r = idx >> 4, c = idx & 15;
        float v = nan0(pt[(size_t)(r0 + r) * GD + c]);
        int rr = r & 15, rb = r >> 4;
        int gg = rr & 7, hi8 = rr >> 3;
        int qq = (c & 7) >> 1, par = c & 1;
        int a_idx = ((c >= 8) ? 2 : 0) + hi8;
        int ln = gg * 4 + qq;
        xf[(rb * 32 + ln) * 8 + a_idx * 2 + par] = __float2half_rn(v);
    }
    if (tid < 256) {
        b1s[tid] = b1[tid];
        b2s[tid] = b2[tid];
    }
    if (tid < 16) {
        b3s[tid] = b3[tid];
        float s = 0.f;
        for (int j = 0; j < ZD; j++) {
            float u = nan0(U[j * RR + tid]);
            s += u * u;
        }
        cn2s[tid] = s;
    }
    cpwait<1>();     // W1/W3 ready; chunk0 in flight
    __syncthreads();

    const int wm = wid >> 3, wn = wid & 7;   // 2 x 8 warps

    // ================= GEMM1: h1 = silu(x @ W1 + b1) -> h1 A-frags =========
#pragma unroll
    for (int mt = 0; mt < 2; mt++) {
        int rb = wm * 2 + mt;
        uint4 Av = *(const uint4*)(smc + OFF_XF + (rb * 32 + lane) * 16);
        uint32_t A[4] = {Av.x, Av.y, Av.z, Av.w};
#pragma unroll
        for (int nt = 0; nt < 4; nt++) {
            float acc[4] = {0.f, 0.f, 0.f, 0.f};
            uint2 Bv = *(const uint2*)(smc + OFF_W1F + ((wn * 4 + nt) * 32 + lane) * 8);
            uint32_t B[2] = {Bv.x, Bv.y};
            mma16(acc, A, B, acc);
            int ntile = wn * 4 + nt, cb = ntile * 8;
            float s0 = silu_f(acc[0] + b1s[cb + 2 * q]);
            float s1 = silu_f(acc[1] + b1s[cb + 2 * q + 1]);
            float s2 = silu_f(acc[2] + b1s[cb + 2 * q]);
            float s3 = silu_f(acc[3] + b1s[cb + 2 * q + 1]);
            int kk = ntile >> 1, half = ntile & 1;
            uint2 pk = make_uint2(packh(s0, s1), packh(s2, s3));
            *(uint2*)(smc + OFF_H1F + ((rb * 16 + kk) * 32 + lane) * 16 + half * 8) = pk;
        }
    }
    __syncthreads();

    // ================= GEMM2: h2 = silu(h1 @ W2 + b2), 8 chunks K=32 =======
    float acc[2][4][4];
#pragma unroll
    for (int mt = 0; mt < 2; mt++)
#pragma unroll
        for (int nt = 0; nt < 4; nt++)
#pragma unroll
            for (int i = 0; i < 4; i++) acc[mt][nt][i] = 0.f;

    for (int c = 0; c < 8; c++) {
        cpwait<0>();
        __syncthreads();
        if (c < 7) {    // prefetch next chunk into the other slot (safe: post-barrier)
#pragma unroll
            for (int i = 0; i < 2; i++) {
                int idx = tid + i * 512;
                cpa16(sb + OFF_RING + ((c + 1) & 1) * 16384 + idx * 16,
                      gw + (size_t)(c + 1) * 16384 + idx * 16);
            }
            cpcommit();
        }
        const char* wb = smc + OFF_RING + (c & 1) * 16384;
#pragma unroll
        for (int ks = 0; ks < 2; ks++) {
            int kk = c * 2 + ks;
            uint4 A0v = *(const uint4*)(smc + OFF_H1F + (((wm * 2 + 0) * 16 + kk) * 32 + lane) * 16);
            uint4 A1v = *(const uint4*)(smc + OFF_H1F + (((wm * 2 + 1) * 16 + kk) * 32 + lane) * 16);
            uint32_t A0[4] = {A0v.x, A0v.y, A0v.z, A0v.w};
            uint32_t A1[4] = {A1v.x, A1v.y, A1v.z, A1v.w};
#pragma unroll
            for (int nt = 0; nt < 4; nt++) {
                uint2 Bv = *(const uint2*)(wb + (((ks * 8 + wn) * 4 + nt) * 32 + lane) * 8);
                uint32_t B[2] = {Bv.x, Bv.y};
                mma16(acc[0][nt], A0, B, acc[0][nt]);
                mma16(acc[1][nt], A1, B, acc[1][nt]);
            }
        }
    }
    __syncthreads();   // all h1f reads done before h2 frags overlay it

    // epilogue -> h2 A-frags (overlay OFF_H1F)
#pragma unroll
    for (int mt = 0; mt < 2; mt++) {
        int rb = wm * 2 + mt;
#pragma unroll
        for (int nt = 0; nt < 4; nt++) {
            int ntile = wn * 4 + nt, cb = ntile * 8;
            float s0 = silu_f(acc[mt][nt][0] + b2s[cb + 2 * q]);
            float s1 = silu_f(acc[mt][nt][1] + b2s[cb + 2 * q + 1]);
            float s2 = silu_f(acc[mt][nt][2] + b2s[cb + 2 * q]);
            float s3 = silu_f(acc[mt][nt][3] + b2s[cb + 2 * q + 1]);
            int kk = ntile >> 1, half = ntile & 1;
            uint2 pk = make_uint2(packh(s0, s1), packh(s2, s3));
            *(uint2*)(smc + OFF_H1F + ((rb * 16 + kk) * 32 + lane) * 16 + half * 8) = pk;
        }
    }
    __syncthreads();

    // ================= GEMM3: h = h2 @ W3 (4-way K-split over warps) =======
    float* hp = (float*)(smc + OFF_RING);   // [4][64][20] fp32 partials
    {
        int rb = wid & 3, wk = wid >> 2;    // rb: 16-row tile, wk: 4-kstep slice
        float a3[2][4] = {{0.f, 0.f, 0.f, 0.f}, {0.f, 0.f, 0.f, 0.f}};
#pragma unroll
        for (int ksl = 0; ksl < 4; ksl++) {
            int kk = wk * 4 + ksl;
            uint4 Av = *(const uint4*)(smc + OFF_H1F + ((rb * 16 + kk) * 32 + lane) * 16);
            uint32_t A[4] = {Av.x, Av.y, Av.z, Av.w};
#pragma unroll
            for (int nt = 0; nt < 2; nt++) {
                uint2 Bv = *(const uint2*)(smc + OFF_W3F + ((kk * 2 + nt) * 32 + lane) * 8);
                uint32_t B[2] = {Bv.x, Bv.y};
                mma16(a3[nt], A, B, a3[nt]);
            }
        }
#pragma unroll
        for (int nt = 0; nt < 2; nt++) {
            int c0 = nt * 8 + 2 * q;
            *(float2*)&hp[(wk * 64 + rb * 16 + g) * 20 + c0]     = make_float2(a3[nt][0], a3[nt][1]);
            *(float2*)&hp[(wk * 64 + rb * 16 + g + 8) * 20 + c0] = make_float2(a3[nt][2], a3[nt][3]);
        }
    }
    __syncthreads();

    // ================= per-row epilogue =================
    if (tid < 64) {
        int row = tid;
        float s[16], fro2 = 0.f;
#pragma unroll
        for (int r = 0; r < 16; r++) {
            float v = b3s[r];
#pragma unroll
            for (int p = 0; p < 4; p++) v += hp[(p * 64 + row) * 20 + r];
            float sr = 2.f / (1.f + __expf(-v));
            s[r] = sr;
            fro2 += sr * sr * cn2s[r];
        }
        float fro = sqrtf(fro2);
        float scale = fminf(2.2627416997969522f / fmaxf(fro, 1e-9f), 1.f);

        float v = dt_norm_g[r0 + row];
        if (isnan(v)) v = 0.f;
        v = fminf(fmaxf(v, 0.f), 1.f);
        float logdt = fminf(-3.f + v * 11.f, 2.7781512503836436f);   // log10(600)
        float dt = fmaxf(expf(logdt * 2.302585092994046f), 1e-30f);
        float lamg = expf(-0.1f * dt);
        g_lamg[r0 + row] = lamg;
#pragma unroll
        for (int r = 0; r < 16; r++) {
            float ss = s[r] * scale;
            float lp = expf(-ss * ss * dt) * lamg;
            g_d[(size_t)(r0 + row) * 16 + r] = lp - lamg;
        }
    }
}

// ============================================================================
// Kernel 2: z_next = lam_g*z + ((lam_para - lam_g) .* (z@U)) @ U^T (unchanged)
// ============================================================================
__global__ void __launch_bounds__(256, 3) dyn_kernel(
    const float* __restrict__ z, const float* __restrict__ U,
    float* __restrict__ out) {
    extern __shared__ float sm2[];
    float* zs = sm2;            // 64*132 = 8448
    float* Us = sm2 + 8448;     // 128*24 = 3072
    float* Ut = sm2 + 11520;    // 16*136 = 2176
    float* cs = sm2 + 13696;    // 64*20  = 1280
    float* lg = sm2 + 14976;    // 64
    const int tid = threadIdx.x;
    const int wid = tid >> 5, lane = tid & 31;
    const int g = lane >> 2, q = lane & 3;
    const int r0 = blockIdx.x * MTILE;

#pragma unroll
    for (int i = 0; i < 8; i++) {
        int idx = tid + i * 256;
        int row = idx >> 5, c4 = (idx & 31) << 2;
        float4 v = *reinterpret_cast<const float4*>(&z[(size_t)(r0 + row) * ZD + c4]);
        v.x = nan0(v.x); v.y = nan0(v.y); v.z = nan0(v.z); v.w = nan0(v.w);
        *reinterpret_cast<float4*>(&zs[row * 132 + c4]) = v;
    }
#pragma unroll
    for (int i = 0; i < 8; i++) {
        int idx = tid + i * 256;
        int j = idx >> 4, r = idx & 15;
        float v = nan0(U[j * RR + r]);
        Us[j * 24 + r] = v;
        Ut[r * 136 + j] = v;
    }
    if (tid < 64) lg[tid] = g_lamg[r0 + tid];
    __syncthreads();

    {
        int mt = wid >> 1, nt = wid & 1;
        int rbase = mt * 16, cbase = nt * 8;
        float acc[4] = {0.f, 0.f, 0.f, 0.f};
#pragma unroll
        for (int k = 0; k < 16; k++) {
            int k0 = k * 8;
            uint32_t a[4] = {
                fbits(zs[(rbase + g) * 132 + k0 + q]),
                fbits(zs[(rbase + g + 8) * 132 + k0 + q]),
                fbits(zs[(rbase + g) * 132 + k0 + q + 4]),
                fbits(zs[(rbase + g + 8) * 132 + k0 + q + 4])};
            uint32_t b[2] = {fbits(Us[(k0 + q) * 24 + cbase + g]),
                             fbits(Us[(k0 + q + 4) * 24 + cbase + g])};
            mma8(acc, a, b, acc);
        }
        int row0 = rbase + g, row1 = rbase + g + 8;
        int c0 = cbase + 2 * q, c1 = c0 + 1;
        cs[row0 * 20 + c0] = acc[0] * g_d[(size_t)(r0 + row0) * 16 + c0];
        cs[row0 * 20 + c1] = acc[1] * g_d[(size_t)(r0 + row0) * 16 + c1];
        cs[row1 * 20 + c0] = acc[2] * g_d[(size_t)(r0 + row1) * 16 + c0];
        cs[row1 * 20 + c1] = acc[3] * g_d[(size_t)(r0 + row1) * 16 + c1];
    }
    __syncthreads();

    {
        int wm = wid >> 1, wn = wid & 1;
        int rbase = wm * 16;
        float acc[8][4];
#pragma unroll
        for (int nt = 0; nt < 8; nt++)
#pragma unroll
            for (int i = 0; i < 4; i++) acc[nt][i] = 0.f;
#pragma unroll
        for (int ks = 0; ks < 2; ks++) {
            int k0 = ks * 8;
            uint32_t a[4] = {
                fbits(cs[(rbase + g) * 20 + k0 + q]),
                fbits(cs[(rbase + g + 8) * 20 + k0 + q]),
                fbits(cs[(rbase + g) * 20 + k0 + q + 4]),
                fbits(cs[(rbase + g + 8) * 20 + k0 + q + 4])};
#pragma unroll
            for (int nt = 0; nt < 8; nt++) {
                int cb = (wn * 8 + nt) * 8;
                uint32_t b[2] = {fbits(Ut[(k0 + q) * 136 + cb + g]),
                                 fbits(Ut[(k0 + q + 4) * 136 + cb + g])};
                mma8(acc[nt], a, b, acc[nt]);
            }
        }
        int row0 = rbase + g, row1 = rbase + g + 8;
        float l0 = lg[row0], l1 = lg[row1];
        size_t gr0 = (size_t)(r0 + row0) * ZD, gr1 = (size_t)(r0 + row1) * ZD;
#pragma unroll
        for (int nt = 0; nt < 8; nt++) {
            int cb = (wn * 8 + nt) * 8;
            int c0 = cb + 2 * q;
            float2 z0 = *reinterpret_cast<const float2*>(&zs[row0 * 132 + c0]);
            float2 o0;
            o0.x = l0 * z0.x + acc[nt][0];
            o0.y = l0 * z0.y + acc[nt][1];
            *reinterpret_cast<float2*>(&out[gr0 + c0]) = o0;
            float2 z1 = *reinterpret_cast<const float2*>(&zs[row1 * 132 + c0]);
            float2 o1;
            o1.x = l1 * z1.x + acc[nt][2];
            o1.y = l1 * z1.y + acc[nt][3];
            *reinterpret_cast<float2*>(&out[gr1 + c0]) = o1;
        }
    }
}

extern "C" void kernel_launch(void* const* d_in, const int* in_sizes, int n_in,
                              void* d_out, int out_size) {
    const float* pt      = (const float*)d_in[0];
    const float* z       = (const float*)d_in[1];
    const float* dt_norm = (const float*)d_in[2];
    const float* base_U  = (const float*)d_in[3];
    const float* W1      = (const float*)d_in[4];
    const float* b1      = (const float*)d_in[5];
    const float* W2      = (const float*)d_in[6];
    const float* b2      = (const float*)d_in[7];
    const float* W3      = (const float*)d_in[8];
    const float* b3      = (const float*)d_in[9];
    float* out = (float*)d_out;

    cudaFuncSetAttribute(mlp_kernel, cudaFuncAttributeMaxDynamicSharedMemorySize, SMEM_BYTES);
    cudaFuncSetAttribute(dyn_kernel, cudaFuncAttributeMaxDynamicSharedMemorySize, 60160);

    prep_kernel<<<288, 256>>>(W1, W2, W3);
    mlp_kernel<<<NBLK, 512, SMEM_BYTES>>>(pt, dt_norm, base_U, b1, b2, b3);
    dyn_kernel<<<NBLK, 256, 60160>>>(z, base_U, out);
}